// round 5
// baseline (speedup 1.0000x reference)
#include <cuda_runtime.h>
#include <stdint.h>

#define NB 32768
#define NE 1024

// add on the FMA pipe: d = a*one + b (one==1, opaque runtime value -> IMAD)
static __device__ __forceinline__ uint32_t fadd(uint32_t a, uint32_t b, uint32_t one) {
    uint32_t d;
    asm("mad.lo.u32 %0, %1, %2, %3;" : "=r"(d) : "r"(a), "r"(one), "r"(b));
    return d;
}

// single LOP3: (a | b) ^ c   (LUT: (0xF0|0xCC)^0xAA = 0x56)
static __device__ __forceinline__ uint32_t lop3_orxor(uint32_t a, uint32_t b, uint32_t c) {
    uint32_t d;
    asm("lop3.b32 %0, %1, %2, %3, 0x56;" : "=r"(d) : "r"(a), "r"(b), "r"(c));
    return d;
}

// rotl(x1, r) ^ x0 in 2 instructions: IMAD.WIDE.U32 (fma pipe) gives
// lo = x1<<r, hi = x1>>(32-r) in one op; LOP3 fuses (lo|hi)^x0.
// mul must be the OPAQUE runtime value (1u<<r)*one so it can't be
// strength-reduced back into shifts.
static __device__ __forceinline__ uint32_t rotx(uint32_t x1, uint32_t x0, uint32_t mul) {
    unsigned long long w;
    asm("mul.wide.u32 %0, %1, %2;" : "=l"(w) : "r"(x1), "r"(mul));
    return lop3_orxor((uint32_t)w, (uint32_t)(w >> 32), x0);
}

struct RotM { uint32_t m13, m15, m26, m6, m17, m29, m16, m24; };

// threefry2x32, key (0,42), block (0,i); returns x0^x1 after 20 rounds
// (jax _threefry_random_bits_partitionable, bit_width=32).
// Caller pre-adds ks1=42 into x1.
static __device__ __forceinline__ uint32_t tf(uint32_t x1, uint32_t one, const RotM& M) {
    const uint32_t KS2 = 0x1BD11BF0u;   // 0x1BD11BDA ^ 42
    uint32_t x0;
    // rounds 1-4  {13,15,26,6}
    x0 = x1;                 x1 = rotx(x1, x0, M.m13);
    x0 = fadd(x0, x1, one);  x1 = rotx(x1, x0, M.m15);
    x0 = fadd(x0, x1, one);  x1 = rotx(x1, x0, M.m26);
    x0 = fadd(x0, x1, one);  x1 = rotx(x1, x0, M.m6);
    x0 += 42u;               x1 += KS2 + 1u;
    // rounds 5-8  {17,29,16,24}
    x0 = fadd(x0, x1, one);  x1 = rotx(x1, x0, M.m17);
    x0 = fadd(x0, x1, one);  x1 = rotx(x1, x0, M.m29);
    x0 = fadd(x0, x1, one);  x1 = rotx(x1, x0, M.m16);
    x0 = fadd(x0, x1, one);  x1 = rotx(x1, x0, M.m24);
    x0 += KS2;               x1 += 2u;
    // rounds 9-12 {13,15,26,6}
    x0 = fadd(x0, x1, one);  x1 = rotx(x1, x0, M.m13);
    x0 = fadd(x0, x1, one);  x1 = rotx(x1, x0, M.m15);
    x0 = fadd(x0, x1, one);  x1 = rotx(x1, x0, M.m26);
    x0 = fadd(x0, x1, one);  x1 = rotx(x1, x0, M.m6);
    /* x0 += ks0 (=0) */     x1 += 45u;
    // rounds 13-16 {17,29,16,24}
    x0 = fadd(x0, x1, one);  x1 = rotx(x1, x0, M.m17);
    x0 = fadd(x0, x1, one);  x1 = rotx(x1, x0, M.m29);
    x0 = fadd(x0, x1, one);  x1 = rotx(x1, x0, M.m16);
    x0 = fadd(x0, x1, one);  x1 = rotx(x1, x0, M.m24);
    x0 += 42u;               x1 += KS2 + 4u;
    // rounds 17-20 {13,15,26,6}
    x0 = fadd(x0, x1, one);  x1 = rotx(x1, x0, M.m13);
    x0 = fadd(x0, x1, one);  x1 = rotx(x1, x0, M.m15);
    x0 = fadd(x0, x1, one);  x1 = rotx(x1, x0, M.m26);
    x0 = fadd(x0, x1, one);  x1 = rotx(x1, x0, M.m6);
    x0 += KS2;               x1 += 5u;
    return x0 ^ x1;
}

__global__ __launch_bounds__(256)
void dnm_kernel(const float4* __restrict__ embeds,
                const float* __restrict__ factors,
                const float4* __restrict__ mask_token,
                float4* __restrict__ out_embeds,
                float4* __restrict__ out_mask,
                uint32_t one) {
    __shared__ uint32_t sh_hist[256];
    __shared__ unsigned long long sh_cand[1040];   // unique keys (bits<<10)|col
    __shared__ int sh_cnt;
    __shared__ int sh_k;
    __shared__ int sh_bucket;
    __shared__ int sh_rem;
    __shared__ unsigned long long sh_thr;

    const int row = blockIdx.x;
    const int tid = threadIdx.x;

    // opaque rotation multipliers (uniform -> URs); defeats strength-reduction
    RotM M;
    M.m13 = (1u << 13) * one;  M.m15 = (1u << 15) * one;
    M.m26 = (1u << 26) * one;  M.m6  = (1u << 6)  * one;
    M.m17 = (1u << 17) * one;  M.m29 = (1u << 29) * one;
    M.m16 = (1u << 16) * one;  M.m24 = (1u << 24) * one;

    // Prefetch streaming data; threefry compute hides the latency.
    const float4 e  = embeds[(size_t)row * (NE / 4) + tid];
    const float4 mt = __ldg(&mask_token[tid]);

    sh_hist[tid] = 0u;
    if (tid == 0) {
        sh_cnt = 0;
        const float f = __ldg(&factors[row]);
        int k = (int)floorf(307.2f * f);   // f32(1024*0.3)*factor, floor
        sh_k = k < 1 ? 1 : k;
    }
    __syncthreads();

    // ---- Phase 1: RNG for 4 contiguous columns + fused histogram ---------
    uint32_t bits[4];
    const uint32_t base = (uint32_t)(row * NE + tid * 4) + 42u;  // +ks1 baked in
    #pragma unroll
    for (int j = 0; j < 4; j++) {
        bits[j] = tf(base + j, one, M);
        atomicAdd(&sh_hist[bits[j] >> 24], 1u);    // bucket = top 8 bits
    }
    __syncthreads();

    // ---- Phase 2: warp 0 scans 256 bins for the k-th-smallest bucket -----
    if (tid < 32) {
        const int lane = tid;
        uint32_t v[8];
        uint32_t s = 0;
        #pragma unroll
        for (int t = 0; t < 8; t++) { v[t] = sh_hist[lane * 8 + t]; s += v[t]; }
        uint32_t incl = s;
        #pragma unroll
        for (int o = 1; o < 32; o <<= 1) {
            uint32_t n = __shfl_up_sync(0xFFFFFFFFu, incl, o);
            if (lane >= o) incl += n;
        }
        const uint32_t excl = incl - s;
        const uint32_t k = (uint32_t)sh_k;
        if (excl < k && k <= incl) {            // unique lane
            uint32_t c = excl;
            #pragma unroll
            for (int t = 0; t < 8; t++) {
                if (k <= c + v[t]) { sh_bucket = lane * 8 + t; sh_rem = (int)(k - c); break; }
                c += v[t];
            }
        }
    }
    __syncthreads();

    // ---- Phase 3: collect boundary-bucket candidates as unique keys ------
    const uint32_t bkt = (uint32_t)sh_bucket;
    #pragma unroll
    for (int j = 0; j < 4; j++) {
        if ((bits[j] >> 24) == bkt) {
            const int p = atomicAdd(&sh_cnt, 1);
            sh_cand[p] = ((unsigned long long)bits[j] << 10) | (unsigned)(tid * 4 + j);
        }
    }
    __syncthreads();

    // ---- Phase 4: warp 0 finds the exact k-th smallest key ---------------
    if (tid < 32) {
        const int c = sh_cnt;
        const int rem = sh_rem;
        for (int idx = tid; idx < c; idx += 32) {
            const unsigned long long key = sh_cand[idx];
            int rank = 0;
            for (int j2 = 0; j2 < c; j2++) rank += (sh_cand[j2] < key);
            if (rank == rem - 1) sh_thr = key;   // keys unique -> one writer
        }
    }
    __syncthreads();

    // ---- Phase 5: apply mask with 32-bit threshold compare ---------------
    const unsigned long long thr = sh_thr;
    const uint32_t thrB = (uint32_t)(thr >> 10);
    const uint32_t thrC = (uint32_t)thr & 1023u;
    const uint32_t cbase = (uint32_t)(tid * 4);

    // masked <=> bits < thrB, or bits == thrB and col <= thrC
    const bool k0 = (bits[0] < thrB) || ((bits[0] == thrB) && (cbase + 0 <= thrC));
    const bool k1 = (bits[1] < thrB) || ((bits[1] == thrB) && (cbase + 1 <= thrC));
    const bool k2 = (bits[2] < thrB) || ((bits[2] == thrB) && (cbase + 2 <= thrC));
    const bool k3 = (bits[3] < thrB) || ((bits[3] == thrB) && (cbase + 3 <= thrC));

    float4 oe, om;
    oe.x = k0 ? mt.x : e.x;  om.x = k0 ? 0.0f : 1.0f;
    oe.y = k1 ? mt.y : e.y;  om.y = k1 ? 0.0f : 1.0f;
    oe.z = k2 ? mt.z : e.z;  om.z = k2 ? 0.0f : 1.0f;
    oe.w = k3 ? mt.w : e.w;  om.w = k3 ? 0.0f : 1.0f;

    out_embeds[(size_t)row * (NE / 4) + tid] = oe;
    out_mask[(size_t)row * (NE / 4) + tid]   = om;
}

extern "C" void kernel_launch(void* const* d_in, const int* in_sizes, int n_in,
                              void* d_out, int out_size) {
    const float4* embeds = (const float4*)d_in[0];     // [32768, 1024] f32
    const float* factors = (const float*)d_in[1];      // [32768] f32
    const float4* mask_token = (const float4*)d_in[2]; // [1, 1024] f32

    float* out = (float*)d_out;
    float4* out_embeds = (float4*)out;                       // [B, E]
    float4* out_mask = (float4*)(out + (size_t)NB * NE);     // [B, E]

    dnm_kernel<<<NB, 256>>>(embeds, factors, mask_token, out_embeds, out_mask, 1u);
}